// round 3
// baseline (speedup 1.0000x reference)
#include <cuda_runtime.h>
#include <cuda_fp16.h>
#include <math.h>

// Problem constants
#define BATCH    64
#define IN_CAPS  2048
#define IN_DIM   16
#define NUM_CAPS 32
#define OUT_DIM  16
#define JD       512            // NUM_CAPS * OUT_DIM
#define NIC      32             // i-chunks per batch in iter kernel
#define IC       (IN_CAPS/NIC)  // 64 i's per block

// Scratch (device globals; allocation-free per harness rules)
__device__ __align__(16) __half g_uhat[(size_t)BATCH * IN_CAPS * JD];  // 128 MB, [b][i][j*16+d]
__device__ float g_spart[(size_t)BATCH * NIC * JD];  // 4 MB, d-major [b][ic][d*32+j]
__device__ float g_out0[(size_t)BATCH * JD];         // d-major [b][d*32+j]
__device__ float g_out1[(size_t)BATCH * JD];

// ---------------------------------------------------------------------------
// K1: u_hat[b,i,j,d] = sum_k W[i,j,d,k] * x[b,i,k]  -> fp16
// One block per i (2048 blocks, 512 threads). Thread t = j*16+d owns one W row
// in registers; x[:,i,:] staged in smem (broadcast LDS, conflict-free).
// ---------------------------------------------------------------------------
__global__ __launch_bounds__(512) void uhat_kernel(
    const float* __restrict__ x, const float* __restrict__ W)
{
    const int i = blockIdx.x;
    const int t = threadIdx.x;          // 0..511  (= j*16 + d)

    __shared__ float4 xs[BATCH][4];     // 64 rows x 16 floats

    if (t < 256) {
        int b = t >> 2, q = t & 3;
        xs[b][q] = ((const float4*)(x + ((size_t)b * IN_CAPS + i) * IN_DIM))[q];
    }

    const float4* Wr = (const float4*)(W + ((size_t)i * JD + t) * IN_DIM);
    float4 w0 = Wr[0], w1 = Wr[1], w2 = Wr[2], w3 = Wr[3];

    __syncthreads();

    __half* out = g_uhat + (size_t)i * JD + t;
    #pragma unroll 4
    for (int b = 0; b < BATCH; b++) {
        float4 a0 = xs[b][0], a1 = xs[b][1], a2 = xs[b][2], a3 = xs[b][3];
        float acc;
        acc = w0.x * a0.x;
        acc = fmaf(w0.y, a0.y, acc);
        acc = fmaf(w0.z, a0.z, acc);
        acc = fmaf(w0.w, a0.w, acc);
        acc = fmaf(w1.x, a1.x, acc);
        acc = fmaf(w1.y, a1.y, acc);
        acc = fmaf(w1.z, a1.z, acc);
        acc = fmaf(w1.w, a1.w, acc);
        acc = fmaf(w2.x, a2.x, acc);
        acc = fmaf(w2.y, a2.y, acc);
        acc = fmaf(w2.z, a2.z, acc);
        acc = fmaf(w2.w, a2.w, acc);
        acc = fmaf(w3.x, a3.x, acc);
        acc = fmaf(w3.y, a3.y, acc);
        acc = fmaf(w3.z, a3.z, acc);
        acc = fmaf(w3.w, a3.w, acc);
        out[(size_t)b * IN_CAPS * JD] = __float2half_rn(acc);
    }
}

// ---------------------------------------------------------------------------
// Fused routing iteration. Lane = j; each lane holds u_hat[b,i,lane,0:15] in
// registers (one 32B contiguous load). Agreement = 16 reg FMAs; softmax =
// one 32-lane butterfly per i per warp. No logits buffer:
//   iter1 logits = <u, out0>;  iter2 logits = <u, out0 + out1>.
// Grid (NIC, BATCH), 8 warps; warp w handles i = i0 + w, i0+w+8, ...
// ---------------------------------------------------------------------------
__global__ __launch_bounds__(256) void iter_kernel(int iter)
{
    const int b    = blockIdx.y;
    const int ic   = blockIdx.x;
    const int t    = threadIdx.x;
    const int w    = t >> 5;
    const int lane = t & 31;            // = j
    const int i0   = ic * IC;

    float vout[16];
    if (iter > 0) {
        #pragma unroll
        for (int d = 0; d < 16; d++) {
            float v = g_out0[(size_t)b * JD + d * 32 + lane];
            if (iter == 2) v += g_out1[(size_t)b * JD + d * 32 + lane];
            vout[d] = v;
        }
    }

    float acc[16];
    #pragma unroll
    for (int d = 0; d < 16; d++) acc[d] = 0.f;

    const __half* uhbase = g_uhat + ((size_t)b * IN_CAPS + i0) * JD + lane * 16;

    #pragma unroll 2
    for (int ii = w; ii < IC; ii += 8) {
        const __half* uh = uhbase + (size_t)ii * JD;
        uint4 r0 = *(const uint4*)uh;
        uint4 r1 = *(const uint4*)(uh + 8);
        float v[16];
        {
            float2 f;
            f = __half22float2(*(const __half2*)&r0.x); v[0]  = f.x; v[1]  = f.y;
            f = __half22float2(*(const __half2*)&r0.y); v[2]  = f.x; v[3]  = f.y;
            f = __half22float2(*(const __half2*)&r0.z); v[4]  = f.x; v[5]  = f.y;
            f = __half22float2(*(const __half2*)&r0.w); v[6]  = f.x; v[7]  = f.y;
            f = __half22float2(*(const __half2*)&r1.x); v[8]  = f.x; v[9]  = f.y;
            f = __half22float2(*(const __half2*)&r1.y); v[10] = f.x; v[11] = f.y;
            f = __half22float2(*(const __half2*)&r1.z); v[12] = f.x; v[13] = f.y;
            f = __half22float2(*(const __half2*)&r1.w); v[14] = f.x; v[15] = f.y;
        }

        if (iter == 0) {
            #pragma unroll
            for (int d = 0; d < 16; d++) acc[d] += v[d];
        } else {
            float a = v[0] * vout[0];
            #pragma unroll
            for (int d = 1; d < 16; d++) a = fmaf(v[d], vout[d], a);

            float m = a;
            #pragma unroll
            for (int o = 16; o; o >>= 1)
                m = fmaxf(m, __shfl_xor_sync(0xffffffffu, m, o));
            float e = __expf(a - m);
            float s = e;
            #pragma unroll
            for (int o = 16; o; o >>= 1)
                s += __shfl_xor_sync(0xffffffffu, s, o);
            float c = e / s;

            #pragma unroll
            for (int d = 0; d < 16; d++) acc[d] = fmaf(c, v[d], acc[d]);
        }
    }

    if (iter == 0) {
        #pragma unroll
        for (int d = 0; d < 16; d++) acc[d] *= (1.0f / NUM_CAPS);
    }

    // Cross-warp reduce (d-major in smem: conflict-free writes and reads)
    __shared__ float red[8][JD];
    #pragma unroll
    for (int d = 0; d < 16; d++) red[w][d * 32 + lane] = acc[d];
    __syncthreads();

    float s1 = 0.f, s2 = 0.f;
    #pragma unroll
    for (int ww = 0; ww < 8; ww++) {
        s1 += red[ww][t];
        s2 += red[ww][t + 256];
    }
    float* sp = g_spart + ((size_t)b * NIC + ic) * JD;
    sp[t]       = s1;
    sp[t + 256] = s2;
}

// ---------------------------------------------------------------------------
// Reduce partials over NIC chunks + squash. d-major positions: t = d*32 + j.
// which: 0 -> g_out0, 1 -> g_out1, 2 -> dout (permuted to [b][j][d]).
// ---------------------------------------------------------------------------
__global__ __launch_bounds__(512) void squash_kernel(int which, float* __restrict__ dout)
{
    const int b = blockIdx.x;
    const int t = threadIdx.x;

    const float* sp = g_spart + (size_t)b * NIC * JD + t;
    float s = 0.f;
    #pragma unroll
    for (int p = 0; p < NIC; p++) s += sp[(size_t)p * JD];

    __shared__ float s2s[NUM_CAPS];
    if (t < NUM_CAPS) s2s[t] = 0.f;
    __syncthreads();
    atomicAdd(&s2s[t & 31], s * s);
    __syncthreads();

    float s2 = s2s[t & 31];
    float scale = s2 / ((1.0f + s2) * sqrtf(s2 + 1e-7f));
    float v = s * scale;

    if (which == 2)      dout[(size_t)b * JD + (t & 31) * 16 + (t >> 5)] = v;
    else if (which == 0) g_out0[(size_t)b * JD + t] = v;
    else                 g_out1[(size_t)b * JD + t] = v;
}

// ---------------------------------------------------------------------------
extern "C" void kernel_launch(void* const* d_in, const int* in_sizes, int n_in,
                              void* d_out, int out_size)
{
    const float* x = (const float*)d_in[0];
    const float* W = (const float*)d_in[1];
    if (in_sizes[0] == (int)((size_t)IN_CAPS * NUM_CAPS * IN_DIM * OUT_DIM)) {
        const float* tmp = x; x = W; W = tmp;
    }
    float* out = (float*)d_out;

    dim3 ig(NIC, BATCH);

    uhat_kernel<<<IN_CAPS, 512>>>(x, W);

    iter_kernel<<<ig, 256>>>(0);
    squash_kernel<<<BATCH, 512>>>(0, out);   // -> g_out0

    iter_kernel<<<ig, 256>>>(1);
    squash_kernel<<<BATCH, 512>>>(1, out);   // -> g_out1

    iter_kernel<<<ig, 256>>>(2);
    squash_kernel<<<BATCH, 512>>>(2, out);   // -> dout
}

// round 4
// speedup vs baseline: 1.0028x; 1.0028x over previous
#include <cuda_runtime.h>
#include <cuda_fp16.h>
#include <math.h>

// Problem constants
#define BATCH    64
#define IN_CAPS  2048
#define IN_DIM   16
#define NUM_CAPS 32
#define OUT_DIM  16
#define JD       512            // NUM_CAPS * OUT_DIM
#define NIC      32             // i-chunks per batch in iter kernel
#define IC       (IN_CAPS/NIC)  // 64 i's per block

// Scratch (device globals; allocation-free per harness rules)
__device__ __align__(16) __half g_uhat[(size_t)BATCH * IN_CAPS * JD];  // 128 MB, [b][i][j*16+d]
__device__ float g_spart[(size_t)BATCH * NIC * JD];  // 4 MB, d-major [b][ic][d*32+j]
__device__ float g_out0[(size_t)BATCH * JD];         // d-major [b][d*32+j]
__device__ float g_out1[(size_t)BATCH * JD];

// ---------------------------------------------------------------------------
// K1: u_hat[b,i,j,d] = sum_k W[i,j,d,k] * x[b,i,k]  -> fp16
// One block per i (2048 blocks, 512 threads). Thread t = j*16+d owns one W row
// in registers; x[:,i,:] staged in smem (broadcast LDS, conflict-free).
// ---------------------------------------------------------------------------
__global__ __launch_bounds__(512) void uhat_kernel(
    const float* __restrict__ x, const float* __restrict__ W)
{
    const int i = blockIdx.x;
    const int t = threadIdx.x;          // 0..511  (= j*16 + d)

    __shared__ float4 xs[BATCH][4];     // 64 rows x 16 floats

    if (t < 256) {
        int b = t >> 2, q = t & 3;
        xs[b][q] = ((const float4*)(x + ((size_t)b * IN_CAPS + i) * IN_DIM))[q];
    }

    const float4* Wr = (const float4*)(W + ((size_t)i * JD + t) * IN_DIM);
    float4 w0 = Wr[0], w1 = Wr[1], w2 = Wr[2], w3 = Wr[3];

    __syncthreads();

    __half* out = g_uhat + (size_t)i * JD + t;
    #pragma unroll 4
    for (int b = 0; b < BATCH; b++) {
        float4 a0 = xs[b][0], a1 = xs[b][1], a2 = xs[b][2], a3 = xs[b][3];
        float acc;
        acc = w0.x * a0.x;
        acc = fmaf(w0.y, a0.y, acc);
        acc = fmaf(w0.z, a0.z, acc);
        acc = fmaf(w0.w, a0.w, acc);
        acc = fmaf(w1.x, a1.x, acc);
        acc = fmaf(w1.y, a1.y, acc);
        acc = fmaf(w1.z, a1.z, acc);
        acc = fmaf(w1.w, a1.w, acc);
        acc = fmaf(w2.x, a2.x, acc);
        acc = fmaf(w2.y, a2.y, acc);
        acc = fmaf(w2.z, a2.z, acc);
        acc = fmaf(w2.w, a2.w, acc);
        acc = fmaf(w3.x, a3.x, acc);
        acc = fmaf(w3.y, a3.y, acc);
        acc = fmaf(w3.z, a3.z, acc);
        acc = fmaf(w3.w, a3.w, acc);
        out[(size_t)b * IN_CAPS * JD] = __float2half_rn(acc);
    }
}

// ---------------------------------------------------------------------------
// Fused routing iteration. Lane = j; each lane holds u_hat[b,i,lane,0:15] in
// registers (one 32B contiguous load). Agreement = 16 reg FMAs; softmax =
// one 32-lane butterfly per i per warp. No logits buffer:
//   iter1 logits = <u, out0>;  iter2 logits = <u, out0 + out1>.
// Grid (NIC, BATCH), 8 warps; warp w handles i = i0 + w, i0+w+8, ...
// ---------------------------------------------------------------------------
__global__ __launch_bounds__(256) void iter_kernel(int iter)
{
    const int b    = blockIdx.y;
    const int ic   = blockIdx.x;
    const int t    = threadIdx.x;
    const int w    = t >> 5;
    const int lane = t & 31;            // = j
    const int i0   = ic * IC;

    float vout[16];
    if (iter > 0) {
        #pragma unroll
        for (int d = 0; d < 16; d++) {
            float v = g_out0[(size_t)b * JD + d * 32 + lane];
            if (iter == 2) v += g_out1[(size_t)b * JD + d * 32 + lane];
            vout[d] = v;
        }
    }

    float acc[16];
    #pragma unroll
    for (int d = 0; d < 16; d++) acc[d] = 0.f;

    const __half* uhbase = g_uhat + ((size_t)b * IN_CAPS + i0) * JD + lane * 16;

    #pragma unroll 2
    for (int ii = w; ii < IC; ii += 8) {
        const __half* uh = uhbase + (size_t)ii * JD;
        uint4 r0 = *(const uint4*)uh;
        uint4 r1 = *(const uint4*)(uh + 8);
        float v[16];
        {
            float2 f;
            f = __half22float2(*(const __half2*)&r0.x); v[0]  = f.x; v[1]  = f.y;
            f = __half22float2(*(const __half2*)&r0.y); v[2]  = f.x; v[3]  = f.y;
            f = __half22float2(*(const __half2*)&r0.z); v[4]  = f.x; v[5]  = f.y;
            f = __half22float2(*(const __half2*)&r0.w); v[6]  = f.x; v[7]  = f.y;
            f = __half22float2(*(const __half2*)&r1.x); v[8]  = f.x; v[9]  = f.y;
            f = __half22float2(*(const __half2*)&r1.y); v[10] = f.x; v[11] = f.y;
            f = __half22float2(*(const __half2*)&r1.z); v[12] = f.x; v[13] = f.y;
            f = __half22float2(*(const __half2*)&r1.w); v[14] = f.x; v[15] = f.y;
        }

        if (iter == 0) {
            #pragma unroll
            for (int d = 0; d < 16; d++) acc[d] += v[d];
        } else {
            float a = v[0] * vout[0];
            #pragma unroll
            for (int d = 1; d < 16; d++) a = fmaf(v[d], vout[d], a);

            float m = a;
            #pragma unroll
            for (int o = 16; o; o >>= 1)
                m = fmaxf(m, __shfl_xor_sync(0xffffffffu, m, o));
            float e = __expf(a - m);
            float s = e;
            #pragma unroll
            for (int o = 16; o; o >>= 1)
                s += __shfl_xor_sync(0xffffffffu, s, o);
            float c = e / s;

            #pragma unroll
            for (int d = 0; d < 16; d++) acc[d] = fmaf(c, v[d], acc[d]);
        }
    }

    if (iter == 0) {
        #pragma unroll
        for (int d = 0; d < 16; d++) acc[d] *= (1.0f / NUM_CAPS);
    }

    // Cross-warp reduce (d-major in smem: conflict-free writes and reads)
    __shared__ float red[8][JD];
    #pragma unroll
    for (int d = 0; d < 16; d++) red[w][d * 32 + lane] = acc[d];
    __syncthreads();

    float s1 = 0.f, s2 = 0.f;
    #pragma unroll
    for (int ww = 0; ww < 8; ww++) {
        s1 += red[ww][t];
        s2 += red[ww][t + 256];
    }
    float* sp = g_spart + ((size_t)b * NIC + ic) * JD;
    sp[t]       = s1;
    sp[t + 256] = s2;
}

// ---------------------------------------------------------------------------
// Reduce partials over NIC chunks + squash. d-major positions: t = d*32 + j.
// which: 0 -> g_out0, 1 -> g_out1, 2 -> dout (permuted to [b][j][d]).
// ---------------------------------------------------------------------------
__global__ __launch_bounds__(512) void squash_kernel(int which, float* __restrict__ dout)
{
    const int b = blockIdx.x;
    const int t = threadIdx.x;

    const float* sp = g_spart + (size_t)b * NIC * JD + t;
    float s = 0.f;
    #pragma unroll
    for (int p = 0; p < NIC; p++) s += sp[(size_t)p * JD];

    __shared__ float s2s[NUM_CAPS];
    if (t < NUM_CAPS) s2s[t] = 0.f;
    __syncthreads();
    atomicAdd(&s2s[t & 31], s * s);
    __syncthreads();

    float s2 = s2s[t & 31];
    float scale = s2 / ((1.0f + s2) * sqrtf(s2 + 1e-7f));
    float v = s * scale;

    if (which == 2)      dout[(size_t)b * JD + (t & 31) * 16 + (t >> 5)] = v;
    else if (which == 0) g_out0[(size_t)b * JD + t] = v;
    else                 g_out1[(size_t)b * JD + t] = v;
}

// ---------------------------------------------------------------------------
extern "C" void kernel_launch(void* const* d_in, const int* in_sizes, int n_in,
                              void* d_out, int out_size)
{
    const float* x = (const float*)d_in[0];
    const float* W = (const float*)d_in[1];
    if (in_sizes[0] == (int)((size_t)IN_CAPS * NUM_CAPS * IN_DIM * OUT_DIM)) {
        const float* tmp = x; x = W; W = tmp;
    }
    float* out = (float*)d_out;

    dim3 ig(NIC, BATCH);

    uhat_kernel<<<IN_CAPS, 512>>>(x, W);

    iter_kernel<<<ig, 256>>>(0);
    squash_kernel<<<BATCH, 512>>>(0, out);   // -> g_out0

    iter_kernel<<<ig, 256>>>(1);
    squash_kernel<<<BATCH, 512>>>(1, out);   // -> g_out1

    iter_kernel<<<ig, 256>>>(2);
    squash_kernel<<<BATCH, 512>>>(2, out);   // -> dout
}

// round 5
// speedup vs baseline: 1.0031x; 1.0003x over previous
#include <cuda_runtime.h>
#include <cuda_fp16.h>
#include <math.h>

// Problem constants
#define BATCH    64
#define IN_CAPS  2048
#define IN_DIM   16
#define NUM_CAPS 32
#define OUT_DIM  16
#define JD       512            // NUM_CAPS * OUT_DIM
#define NIC      32             // i-chunks per batch in iter kernel
#define IC       (IN_CAPS/NIC)  // 64 i's per block

// Scratch (device globals; allocation-free per harness rules)
__device__ __align__(16) __half g_uhat[(size_t)BATCH * IN_CAPS * JD];  // 128 MB, [b][i][j*16+d]
__device__ float g_spart[(size_t)BATCH * NIC * JD];  // 4 MB, d-major [b][ic][d*32+j]
__device__ float g_out0[(size_t)BATCH * JD];         // d-major [b][d*32+j]
__device__ float g_out1[(size_t)BATCH * JD];

// ---------------------------------------------------------------------------
// K1: u_hat[b,i,j,d] = sum_k W[i,j,d,k] * x[b,i,k]  -> fp16
// One block per i (2048 blocks, 512 threads). Thread t = j*16+d owns one W row
// in registers; x[:,i,:] staged in smem (broadcast LDS, conflict-free).
// ---------------------------------------------------------------------------
__global__ __launch_bounds__(512) void uhat_kernel(
    const float* __restrict__ x, const float* __restrict__ W)
{
    const int i = blockIdx.x;
    const int t = threadIdx.x;          // 0..511  (= j*16 + d)

    __shared__ float4 xs[BATCH][4];     // 64 rows x 16 floats

    if (t < 256) {
        int b = t >> 2, q = t & 3;
        xs[b][q] = ((const float4*)(x + ((size_t)b * IN_CAPS + i) * IN_DIM))[q];
    }

    const float4* Wr = (const float4*)(W + ((size_t)i * JD + t) * IN_DIM);
    float4 w0 = Wr[0], w1 = Wr[1], w2 = Wr[2], w3 = Wr[3];

    __syncthreads();

    __half* out = g_uhat + (size_t)i * JD + t;
    #pragma unroll 4
    for (int b = 0; b < BATCH; b++) {
        float4 a0 = xs[b][0], a1 = xs[b][1], a2 = xs[b][2], a3 = xs[b][3];
        float acc;
        acc = w0.x * a0.x;
        acc = fmaf(w0.y, a0.y, acc);
        acc = fmaf(w0.z, a0.z, acc);
        acc = fmaf(w0.w, a0.w, acc);
        acc = fmaf(w1.x, a1.x, acc);
        acc = fmaf(w1.y, a1.y, acc);
        acc = fmaf(w1.z, a1.z, acc);
        acc = fmaf(w1.w, a1.w, acc);
        acc = fmaf(w2.x, a2.x, acc);
        acc = fmaf(w2.y, a2.y, acc);
        acc = fmaf(w2.z, a2.z, acc);
        acc = fmaf(w2.w, a2.w, acc);
        acc = fmaf(w3.x, a3.x, acc);
        acc = fmaf(w3.y, a3.y, acc);
        acc = fmaf(w3.z, a3.z, acc);
        acc = fmaf(w3.w, a3.w, acc);
        out[(size_t)b * IN_CAPS * JD] = __float2half_rn(acc);
    }
}

// ---------------------------------------------------------------------------
// Fused routing iteration. Lane = j; each lane holds u_hat[b,i,lane,0:15] in
// registers (one 32B contiguous load). Agreement = 16 reg FMAs; softmax =
// one 32-lane butterfly per i per warp. No logits buffer:
//   iter1 logits = <u, out0>;  iter2 logits = <u, out0 + out1>.
// Grid (NIC, BATCH), 8 warps; warp w handles i = i0 + w, i0+w+8, ...
// ---------------------------------------------------------------------------
__global__ __launch_bounds__(256) void iter_kernel(int iter)
{
    const int b    = blockIdx.y;
    const int ic   = blockIdx.x;
    const int t    = threadIdx.x;
    const int w    = t >> 5;
    const int lane = t & 31;            // = j
    const int i0   = ic * IC;

    float vout[16];
    if (iter > 0) {
        #pragma unroll
        for (int d = 0; d < 16; d++) {
            float v = g_out0[(size_t)b * JD + d * 32 + lane];
            if (iter == 2) v += g_out1[(size_t)b * JD + d * 32 + lane];
            vout[d] = v;
        }
    }

    float acc[16];
    #pragma unroll
    for (int d = 0; d < 16; d++) acc[d] = 0.f;

    const __half* uhbase = g_uhat + ((size_t)b * IN_CAPS + i0) * JD + lane * 16;

    #pragma unroll 2
    for (int ii = w; ii < IC; ii += 8) {
        const __half* uh = uhbase + (size_t)ii * JD;
        uint4 r0 = *(const uint4*)uh;
        uint4 r1 = *(const uint4*)(uh + 8);
        float v[16];
        {
            float2 f;
            f = __half22float2(*(const __half2*)&r0.x); v[0]  = f.x; v[1]  = f.y;
            f = __half22float2(*(const __half2*)&r0.y); v[2]  = f.x; v[3]  = f.y;
            f = __half22float2(*(const __half2*)&r0.z); v[4]  = f.x; v[5]  = f.y;
            f = __half22float2(*(const __half2*)&r0.w); v[6]  = f.x; v[7]  = f.y;
            f = __half22float2(*(const __half2*)&r1.x); v[8]  = f.x; v[9]  = f.y;
            f = __half22float2(*(const __half2*)&r1.y); v[10] = f.x; v[11] = f.y;
            f = __half22float2(*(const __half2*)&r1.z); v[12] = f.x; v[13] = f.y;
            f = __half22float2(*(const __half2*)&r1.w); v[14] = f.x; v[15] = f.y;
        }

        if (iter == 0) {
            #pragma unroll
            for (int d = 0; d < 16; d++) acc[d] += v[d];
        } else {
            float a = v[0] * vout[0];
            #pragma unroll
            for (int d = 1; d < 16; d++) a = fmaf(v[d], vout[d], a);

            float m = a;
            #pragma unroll
            for (int o = 16; o; o >>= 1)
                m = fmaxf(m, __shfl_xor_sync(0xffffffffu, m, o));
            float e = __expf(a - m);
            float s = e;
            #pragma unroll
            for (int o = 16; o; o >>= 1)
                s += __shfl_xor_sync(0xffffffffu, s, o);
            float c = e / s;

            #pragma unroll
            for (int d = 0; d < 16; d++) acc[d] = fmaf(c, v[d], acc[d]);
        }
    }

    if (iter == 0) {
        #pragma unroll
        for (int d = 0; d < 16; d++) acc[d] *= (1.0f / NUM_CAPS);
    }

    // Cross-warp reduce (d-major in smem: conflict-free writes and reads)
    __shared__ float red[8][JD];
    #pragma unroll
    for (int d = 0; d < 16; d++) red[w][d * 32 + lane] = acc[d];
    __syncthreads();

    float s1 = 0.f, s2 = 0.f;
    #pragma unroll
    for (int ww = 0; ww < 8; ww++) {
        s1 += red[ww][t];
        s2 += red[ww][t + 256];
    }
    float* sp = g_spart + ((size_t)b * NIC + ic) * JD;
    sp[t]       = s1;
    sp[t + 256] = s2;
}

// ---------------------------------------------------------------------------
// Reduce partials over NIC chunks + squash. d-major positions: t = d*32 + j.
// which: 0 -> g_out0, 1 -> g_out1, 2 -> dout (permuted to [b][j][d]).
// ---------------------------------------------------------------------------
__global__ __launch_bounds__(512) void squash_kernel(int which, float* __restrict__ dout)
{
    const int b = blockIdx.x;
    const int t = threadIdx.x;

    const float* sp = g_spart + (size_t)b * NIC * JD + t;
    float s = 0.f;
    #pragma unroll
    for (int p = 0; p < NIC; p++) s += sp[(size_t)p * JD];

    __shared__ float s2s[NUM_CAPS];
    if (t < NUM_CAPS) s2s[t] = 0.f;
    __syncthreads();
    atomicAdd(&s2s[t & 31], s * s);
    __syncthreads();

    float s2 = s2s[t & 31];
    float scale = s2 / ((1.0f + s2) * sqrtf(s2 + 1e-7f));
    float v = s * scale;

    if (which == 2)      dout[(size_t)b * JD + (t & 31) * 16 + (t >> 5)] = v;
    else if (which == 0) g_out0[(size_t)b * JD + t] = v;
    else                 g_out1[(size_t)b * JD + t] = v;
}

// ---------------------------------------------------------------------------
extern "C" void kernel_launch(void* const* d_in, const int* in_sizes, int n_in,
                              void* d_out, int out_size)
{
    const float* x = (const float*)d_in[0];
    const float* W = (const float*)d_in[1];
    if (in_sizes[0] == (int)((size_t)IN_CAPS * NUM_CAPS * IN_DIM * OUT_DIM)) {
        const float* tmp = x; x = W; W = tmp;
    }
    float* out = (float*)d_out;

    dim3 ig(NIC, BATCH);

    uhat_kernel<<<IN_CAPS, 512>>>(x, W);

    iter_kernel<<<ig, 256>>>(0);
    squash_kernel<<<BATCH, 512>>>(0, out);   // -> g_out0

    iter_kernel<<<ig, 256>>>(1);
    squash_kernel<<<BATCH, 512>>>(1, out);   // -> g_out1

    iter_kernel<<<ig, 256>>>(2);
    squash_kernel<<<BATCH, 512>>>(2, out);   // -> dout
}

// round 6
// speedup vs baseline: 1.1569x; 1.1533x over previous
#include <cuda_runtime.h>
#include <cuda_fp16.h>
#include <math.h>

// Problem constants
#define BATCH    64
#define IN_CAPS  2048
#define IN_DIM   16
#define NUM_CAPS 32
#define OUT_DIM  16
#define JD       512            // NUM_CAPS * OUT_DIM
#define NIC      32             // i-chunks per batch in iter kernel
#define IC       (IN_CAPS/NIC)  // 64 i's per block

// Scratch (device globals; allocation-free per harness rules)
__device__ __align__(16) __half g_uhat[(size_t)BATCH * IN_CAPS * JD];  // 128 MB, [b][i][j*16+d]
__device__ float g_spart[(size_t)BATCH * NIC * JD];  // 4 MB, d-major [b][ic][d*32+j]
__device__ float g_out0[(size_t)BATCH * JD];         // d-major [b][d*32+j]
__device__ float g_out1[(size_t)BATCH * JD];

// ---- packed f32x2 helpers (sm_103a) ---------------------------------------
static __device__ __forceinline__ unsigned long long pack2(float lo, float hi) {
    unsigned long long r;
    asm("mov.b64 %0, {%1, %2};" : "=l"(r) : "f"(lo), "f"(hi));
    return r;
}
#define FMA2(d, a, b, c) asm("fma.rn.f32x2 %0, %1, %2, %3;" : "=l"(d) : "l"(a), "l"(b), "l"(c))
#define MUL2(d, a, b)    asm("mul.rn.f32x2 %0, %1, %2;"     : "=l"(d) : "l"(a), "l"(b))

// ---------------------------------------------------------------------------
// K1: u_hat[b,i,j,d] = sum_k W[i,j,d,k] * x[b,i,k]  -> fp16
// One block per i, 512 threads (t = j*16+d). x staged in smem pre-packed as
// (b, b+1) f32x2 pairs; W row held in regs as (w,w) pairs. Inner product over
// k done with fma.rn.f32x2: 2 batches per 16 packed FMAs (halves FMA issues).
// ---------------------------------------------------------------------------
__global__ __launch_bounds__(512) void uhat_kernel(
    const float* __restrict__ x, const float* __restrict__ W)
{
    const int i = blockIdx.x;
    const int t = threadIdx.x;          // 0..511

    __shared__ unsigned long long xp[32][16];   // 32 b-pairs x 16 k

    {
        int p = t >> 4, k = t & 15;     // 512 threads cover all 32*16
        float lo = x[((size_t)(2 * p)     * IN_CAPS + i) * IN_DIM + k];
        float hi = x[((size_t)(2 * p + 1) * IN_CAPS + i) * IN_DIM + k];
        xp[p][k] = pack2(lo, hi);
    }

    const float4* Wr = (const float4*)(W + ((size_t)i * JD + t) * IN_DIM);
    float4 w0 = Wr[0], w1 = Wr[1], w2 = Wr[2], w3 = Wr[3];
    unsigned long long wp[16];
    wp[0]  = pack2(w0.x, w0.x); wp[1]  = pack2(w0.y, w0.y);
    wp[2]  = pack2(w0.z, w0.z); wp[3]  = pack2(w0.w, w0.w);
    wp[4]  = pack2(w1.x, w1.x); wp[5]  = pack2(w1.y, w1.y);
    wp[6]  = pack2(w1.z, w1.z); wp[7]  = pack2(w1.w, w1.w);
    wp[8]  = pack2(w2.x, w2.x); wp[9]  = pack2(w2.y, w2.y);
    wp[10] = pack2(w2.z, w2.z); wp[11] = pack2(w2.w, w2.w);
    wp[12] = pack2(w3.x, w3.x); wp[13] = pack2(w3.y, w3.y);
    wp[14] = pack2(w3.z, w3.z); wp[15] = pack2(w3.w, w3.w);

    __syncthreads();

    __half* out = g_uhat + (size_t)i * JD + t;
    #pragma unroll 4
    for (int p = 0; p < 32; p++) {
        const ulonglong2* ap = (const ulonglong2*)xp[p];
        ulonglong2 a0 = ap[0], a1 = ap[1], a2 = ap[2], a3 = ap[3];
        ulonglong2 a4 = ap[4], a5 = ap[5], a6 = ap[6], a7 = ap[7];
        unsigned long long acc;
        MUL2(acc, wp[0],  a0.x);
        FMA2(acc, wp[1],  a0.y, acc);
        FMA2(acc, wp[2],  a1.x, acc);
        FMA2(acc, wp[3],  a1.y, acc);
        FMA2(acc, wp[4],  a2.x, acc);
        FMA2(acc, wp[5],  a2.y, acc);
        FMA2(acc, wp[6],  a3.x, acc);
        FMA2(acc, wp[7],  a3.y, acc);
        FMA2(acc, wp[8],  a4.x, acc);
        FMA2(acc, wp[9],  a4.y, acc);
        FMA2(acc, wp[10], a5.x, acc);
        FMA2(acc, wp[11], a5.y, acc);
        FMA2(acc, wp[12], a6.x, acc);
        FMA2(acc, wp[13], a6.y, acc);
        FMA2(acc, wp[14], a7.x, acc);
        FMA2(acc, wp[15], a7.y, acc);
        float lo, hi;
        asm("mov.b64 {%0, %1}, %2;" : "=f"(lo), "=f"(hi) : "l"(acc));
        out[(size_t)(2 * p)     * IN_CAPS * JD] = __float2half_rn(lo);
        out[(size_t)(2 * p + 1) * IN_CAPS * JD] = __float2half_rn(hi);
    }
}

// ---------------------------------------------------------------------------
// Fused routing iteration. Lane = j; lane loads u_hat[b,i,lane,0:15] (32B).
// Agreement dot in half2 (8 HFMA2), softmax = one 32-lane butterfly per i.
// vout kept as half2 (8 regs); u_hat kept packed until use. Two i's in
// flight per warp step (4 front-batched LDG.128). 4 blocks/SM forced.
//   iter1 logits = <u, out0>;  iter2 logits = <u, out0 + out1>.
// ---------------------------------------------------------------------------
__global__ __launch_bounds__(256, 4) void iter_kernel(int iter)
{
    const int b    = blockIdx.y;
    const int ic   = blockIdx.x;
    const int t    = threadIdx.x;
    const int w    = t >> 5;
    const int lane = t & 31;            // = j
    const int i0   = ic * IC;

    __half2 vout2[8];
    if (iter > 0) {
        #pragma unroll
        for (int d2 = 0; d2 < 8; d2++) {
            float f0 = g_out0[(size_t)b * JD + (2 * d2)     * 32 + lane];
            float f1 = g_out0[(size_t)b * JD + (2 * d2 + 1) * 32 + lane];
            if (iter == 2) {
                f0 += g_out1[(size_t)b * JD + (2 * d2)     * 32 + lane];
                f1 += g_out1[(size_t)b * JD + (2 * d2 + 1) * 32 + lane];
            }
            vout2[d2] = __floats2half2_rn(f0, f1);
        }
    }

    float acc[16];
    #pragma unroll
    for (int d = 0; d < 16; d++) acc[d] = 0.f;

    const __half* uhbase = g_uhat + ((size_t)b * IN_CAPS + i0) * JD + lane * 16;

    #pragma unroll
    for (int step = 0; step < 4; step++) {
        const int iiA = w + step * 16;
        const int iiB = iiA + 8;
        const uint4* pA = (const uint4*)(uhbase + (size_t)iiA * JD);
        const uint4* pB = (const uint4*)(uhbase + (size_t)iiB * JD);
        uint4 ra0 = pA[0], ra1 = pA[1];     // i = iiA : d 0..7, 8..15
        uint4 rb0 = pB[0], rb1 = pB[1];     // i = iiB

        #pragma unroll
        for (int half_sel = 0; half_sel < 2; half_sel++) {
            uint4 r0 = half_sel ? rb0 : ra0;
            uint4 r1 = half_sel ? rb1 : ra1;
            const __half2* v2 = (const __half2*)&r0;   // 4 pairs
            const __half2* v3 = (const __half2*)&r1;   // 4 pairs

            if (iter == 0) {
                #pragma unroll
                for (int d2 = 0; d2 < 4; d2++) {
                    float2 f = __half22float2(v2[d2]);
                    acc[2 * d2]     += f.x;
                    acc[2 * d2 + 1] += f.y;
                    float2 g = __half22float2(v3[d2]);
                    acc[8 + 2 * d2]     += g.x;
                    acc[8 + 2 * d2 + 1] += g.y;
                }
            } else {
                __half2 h = __hmul2(v2[0], vout2[0]);
                h = __hfma2(v2[1], vout2[1], h);
                h = __hfma2(v2[2], vout2[2], h);
                h = __hfma2(v2[3], vout2[3], h);
                h = __hfma2(v3[0], vout2[4], h);
                h = __hfma2(v3[1], vout2[5], h);
                h = __hfma2(v3[2], vout2[6], h);
                h = __hfma2(v3[3], vout2[7], h);
                float a = __low2float(h) + __high2float(h);

                float m = a;
                #pragma unroll
                for (int o = 16; o; o >>= 1)
                    m = fmaxf(m, __shfl_xor_sync(0xffffffffu, m, o));
                float e = __expf(a - m);
                float s = e;
                #pragma unroll
                for (int o = 16; o; o >>= 1)
                    s += __shfl_xor_sync(0xffffffffu, s, o);
                float c = e / s;

                #pragma unroll
                for (int d2 = 0; d2 < 4; d2++) {
                    float2 f = __half22float2(v2[d2]);
                    acc[2 * d2]     = fmaf(c, f.x, acc[2 * d2]);
                    acc[2 * d2 + 1] = fmaf(c, f.y, acc[2 * d2 + 1]);
                    float2 g = __half22float2(v3[d2]);
                    acc[8 + 2 * d2]     = fmaf(c, g.x, acc[8 + 2 * d2]);
                    acc[8 + 2 * d2 + 1] = fmaf(c, g.y, acc[8 + 2 * d2 + 1]);
                }
            }
        }
    }

    if (iter == 0) {
        #pragma unroll
        for (int d = 0; d < 16; d++) acc[d] *= (1.0f / NUM_CAPS);
    }

    // Cross-warp reduce (d-major in smem: conflict-free)
    __shared__ float red[8][JD];
    #pragma unroll
    for (int d = 0; d < 16; d++) red[w][d * 32 + lane] = acc[d];
    __syncthreads();

    float s1 = 0.f, s2 = 0.f;
    #pragma unroll
    for (int ww = 0; ww < 8; ww++) {
        s1 += red[ww][t];
        s2 += red[ww][t + 256];
    }
    float* sp = g_spart + ((size_t)b * NIC + ic) * JD;
    sp[t]       = s1;
    sp[t + 256] = s2;
}

// ---------------------------------------------------------------------------
// Reduce partials over NIC chunks + squash. d-major positions: t = d*32 + j.
// which: 0 -> g_out0, 1 -> g_out1, 2 -> dout (permuted to [b][j][d]).
// ---------------------------------------------------------------------------
__global__ __launch_bounds__(512) void squash_kernel(int which, float* __restrict__ dout)
{
    const int b = blockIdx.x;
    const int t = threadIdx.x;

    const float* sp = g_spart + (size_t)b * NIC * JD + t;
    float s = 0.f;
    #pragma unroll
    for (int p = 0; p < NIC; p++) s += sp[(size_t)p * JD];

    __shared__ float s2s[NUM_CAPS];
    if (t < NUM_CAPS) s2s[t] = 0.f;
    __syncthreads();
    atomicAdd(&s2s[t & 31], s * s);
    __syncthreads();

    float s2 = s2s[t & 31];
    float scale = s2 / ((1.0f + s2) * sqrtf(s2 + 1e-7f));
    float v = s * scale;

    if (which == 2)      dout[(size_t)b * JD + (t & 31) * 16 + (t >> 5)] = v;
    else if (which == 0) g_out0[(size_t)b * JD + t] = v;
    else                 g_out1[(size_t)b * JD + t] = v;
}

// ---------------------------------------------------------------------------
extern "C" void kernel_launch(void* const* d_in, const int* in_sizes, int n_in,
                              void* d_out, int out_size)
{
    const float* x = (const float*)d_in[0];
    const float* W = (const float*)d_in[1];
    if (in_sizes[0] == (int)((size_t)IN_CAPS * NUM_CAPS * IN_DIM * OUT_DIM)) {
        const float* tmp = x; x = W; W = tmp;
    }
    float* out = (float*)d_out;

    dim3 ig(NIC, BATCH);

    uhat_kernel<<<IN_CAPS, 512>>>(x, W);

    iter_kernel<<<ig, 256>>>(0);
    squash_kernel<<<BATCH, 512>>>(0, out);   // -> g_out0

    iter_kernel<<<ig, 256>>>(1);
    squash_kernel<<<BATCH, 512>>>(1, out);   // -> g_out1

    iter_kernel<<<ig, 256>>>(2);
    squash_kernel<<<BATCH, 512>>>(2, out);   // -> dout
}